// round 1
// baseline (speedup 1.0000x reference)
#include <cuda_runtime.h>
#include <math.h>

#define BB 32
#define SS 2048
#define HH 1024
#define UU 128
#define CHUNKS 32
#define SC (SS / CHUNKS)   // 64 rows per chunk
#define H4 (HH / 4)        // 256 float4 per row

// ---- device scratch (no runtime allocation allowed) ----
__device__ float g_v[BB * HH];                 // v[b,h] = sum_k W[h,k] * h_t[b,k]
__device__ float g_pm[BB * CHUNKS];            // per-chunk running max
__device__ float g_pl[BB * CHUNKS];            // per-chunk denom
__device__ float g_pacc[BB * CHUNKS * HH];     // per-chunk unnormalized context
__device__ float g_pre[BB * 2 * HH];           // [context ; h_t]
__device__ float g_pout[16 * BB * UU];         // partial outputs of final GEMM

// ============================================================
// K1: v[b,h] = dot(w_score[h, :], h_t[b, :])   (h_t = hidden[b, S-1, :])
// Tiled: block handles 32 h-rows x all 32 batches; W read exactly once (4MB).
// ============================================================
__global__ void k_v(const float* __restrict__ hidden, const float* __restrict__ wsc) {
    __shared__ float sht[32][65];   // [b][k]  (+1 pad)
    __shared__ float swt[32][65];   // [hh][k] (+1 pad: avoids 32-way conflicts)
    const int t = threadIdx.x;          // 256 threads
    const int h0 = blockIdx.x * 32;     // 32 blocks

    float acc[4] = {0.f, 0.f, 0.f, 0.f};

    for (int k0 = 0; k0 < HH; k0 += 64) {
        #pragma unroll
        for (int i = 0; i < 8; i++) {
            int idx = t + i * 256;
            int b = idx >> 6, k = idx & 63;
            sht[b][k] = hidden[((size_t)b * SS + (SS - 1)) * HH + k0 + k];
        }
        #pragma unroll
        for (int i = 0; i < 8; i++) {
            int idx = t + i * 256;
            int hh = idx >> 6, k = idx & 63;
            swt[hh][k] = wsc[(size_t)(h0 + hh) * HH + k0 + k];
        }
        __syncthreads();
        #pragma unroll
        for (int j = 0; j < 4; j++) {
            int o = t + j * 256;
            int b = o >> 5, hh = o & 31;
            float a = 0.f;
            #pragma unroll 8
            for (int k = 0; k < 64; k++) a += swt[hh][k] * sht[b][k];
            acc[j] += a;
        }
        __syncthreads();
    }
    #pragma unroll
    for (int j = 0; j < 4; j++) {
        int o = t + j * 256;
        int b = o >> 5, hh = o & 31;
        g_v[b * HH + h0 + hh] = acc[j];
    }
}

// ============================================================
// K2: single-pass online-softmax attention over one (batch, s-chunk).
// Reads each hidden row once; score via block reduce; flash-style rescale.
// ============================================================
__global__ void k_attn(const float* __restrict__ hidden) {
    const int b = blockIdx.y;
    const int c = blockIdx.x;
    const int t = threadIdx.x;   // 256 threads, thread t owns h in [4t, 4t+4)

    const float4 v4 = reinterpret_cast<const float4*>(g_v)[b * H4 + t];
    const float4* hid = reinterpret_cast<const float4*>(hidden) + (size_t)b * SS * H4;

    __shared__ float red[8];
    __shared__ float sscore;

    float4 acc = make_float4(0.f, 0.f, 0.f, 0.f);
    float m = -INFINITY, l = 0.f;
    const int s0 = c * SC;

    float4 cur = hid[(size_t)s0 * H4 + t];   // prefetch row 0
    for (int i = 0; i < SC; i++) {
        float4 nxt = make_float4(0.f, 0.f, 0.f, 0.f);
        if (i + 1 < SC) nxt = hid[(size_t)(s0 + i + 1) * H4 + t];  // prefetch next row

        // partial dot with v, then block reduce (8 warps)
        float p = cur.x * v4.x + cur.y * v4.y + cur.z * v4.z + cur.w * v4.w;
        #pragma unroll
        for (int o = 16; o > 0; o >>= 1) p += __shfl_xor_sync(0xffffffffu, p, o);
        if ((t & 31) == 0) red[t >> 5] = p;
        __syncthreads();
        if (t < 8) {
            float q = red[t];
            #pragma unroll
            for (int o = 4; o > 0; o >>= 1) q += __shfl_xor_sync(0xffu, q, o);
            if (t == 0) sscore = q;
        }
        __syncthreads();
        const float score = sscore;

        // online softmax update
        const float mn = fmaxf(m, score);
        const float sc = __expf(m - mn);       // 0 on first iter (m = -inf)
        const float pp = __expf(score - mn);
        l = l * sc + pp;
        acc.x = acc.x * sc + pp * cur.x;
        acc.y = acc.y * sc + pp * cur.y;
        acc.z = acc.z * sc + pp * cur.z;
        acc.w = acc.w * sc + pp * cur.w;
        m = mn;
        cur = nxt;
    }

    if (t == 0) { g_pm[b * CHUNKS + c] = m; g_pl[b * CHUNKS + c] = l; }
    reinterpret_cast<float4*>(g_pacc)[((size_t)b * CHUNKS + c) * H4 + t] = acc;
}

// ============================================================
// K3: merge chunk partials -> context; build pre = [context ; h_t]
// ============================================================
__global__ void k_combine(const float* __restrict__ hidden) {
    const int b = blockIdx.x;
    const int t = threadIdx.x;   // 256 threads
    __shared__ float w[CHUNKS];
    __shared__ float sinvL;

    if (t == 0) {
        float M = -INFINITY;
        for (int c = 0; c < CHUNKS; c++) M = fmaxf(M, g_pm[b * CHUNKS + c]);
        float L = 0.f;
        for (int c = 0; c < CHUNKS; c++) {
            float e = __expf(g_pm[b * CHUNKS + c] - M);
            w[c] = e;
            L += g_pl[b * CHUNKS + c] * e;
        }
        sinvL = 1.f / L;
    }
    __syncthreads();
    const float invL = sinvL;

    float4 ctx = make_float4(0.f, 0.f, 0.f, 0.f);
    for (int c = 0; c < CHUNKS; c++) {
        const float e = w[c];
        const float4 a = reinterpret_cast<const float4*>(g_pacc)[((size_t)b * CHUNKS + c) * H4 + t];
        ctx.x += e * a.x; ctx.y += e * a.y; ctx.z += e * a.z; ctx.w += e * a.w;
    }
    ctx.x *= invL; ctx.y *= invL; ctx.z *= invL; ctx.w *= invL;

    reinterpret_cast<float4*>(g_pre)[b * (2 * H4) + t] = ctx;
    const float4 htv = reinterpret_cast<const float4*>(hidden)[((size_t)b * SS + (SS - 1)) * H4 + t];
    reinterpret_cast<float4*>(g_pre)[b * (2 * H4) + H4 + t] = htv;
}

// ============================================================
// K4: partial final GEMM — block bi covers j in [bi*128, bi*128+128);
// w_out read exactly once (1 MB total). acc[32] per thread (all batches).
// ============================================================
__global__ void k_outp(const float* __restrict__ wout) {
    const int bi = blockIdx.x;   // 16 blocks
    const int t = threadIdx.x;   // 128 threads, t = output unit u
    const int j0 = bi * 128;

    __shared__ float spre[32][128];
    #pragma unroll
    for (int i = 0; i < 32; i++) spre[i][t] = g_pre[i * (2 * HH) + j0 + t];
    __syncthreads();

    float acc[32];
    #pragma unroll
    for (int b = 0; b < 32; b++) acc[b] = 0.f;

    #pragma unroll 2
    for (int jj = 0; jj < 128; jj++) {
        const float wv = wout[(size_t)(j0 + jj) * UU + t];
        #pragma unroll
        for (int b = 0; b < 32; b++) acc[b] += spre[b][jj] * wv;
    }
    #pragma unroll
    for (int b = 0; b < 32; b++) g_pout[((size_t)bi * 32 + b) * UU + t] = acc[b];
}

// K5: reduce 16 partials + tanh -> output
__global__ void k_outf(float* __restrict__ out) {
    const int b = blockIdx.x;   // 32 blocks
    const int t = threadIdx.x;  // 128 threads
    float a = 0.f;
    #pragma unroll
    for (int i = 0; i < 16; i++) a += g_pout[((size_t)i * 32 + b) * UU + t];
    out[b * UU + t] = tanhf(a);
}

extern "C" void kernel_launch(void* const* d_in, const int* in_sizes, int n_in,
                              void* d_out, int out_size) {
    const float* hidden = (const float*)d_in[0];  // (32, 2048, 1024) f32
    const float* wsc    = (const float*)d_in[1];  // (1024, 1024) f32
    const float* wout   = (const float*)d_in[2];  // (2048, 128) f32
    float* out = (float*)d_out;                   // (32, 128) f32

    k_v<<<HH / 32, 256>>>(hidden, wsc);
    dim3 grid_attn(CHUNKS, BB);
    k_attn<<<grid_attn, 256>>>(hidden);
    k_combine<<<BB, 256>>>(hidden);
    k_outp<<<16, 128>>>(wout);
    k_outf<<<BB, UU>>>(out);
}

// round 2
// speedup vs baseline: 1.4490x; 1.4490x over previous
#include <cuda_runtime.h>
#include <math.h>

#define BB 32
#define SS 2048
#define HH 1024
#define UU 128
#define H4 (HH / 4)        // 256 float4 per row
#define KC 4               // split-K for k_v
#define NCB 8              // attn chunk-group blocks per batch
#define WPB 8              // warps per attn block
#define NCHUNK (NCB * WPB) // 64 chunks per batch (one per warp)
#define RPW (SS / NCHUNK)  // 32 rows per warp
#define JC 64              // split-K blocks for output GEMM
#define JCW (2 * HH / JC)  // 32 j-rows per block

// ---- device scratch (no runtime allocation allowed) ----
__device__ float g_vp[KC * BB * HH];            // split-K partials of v = W @ h_t
__device__ float g_pm[BB * NCHUNK];             // per-chunk running max
__device__ float g_pl[BB * NCHUNK];             // per-chunk denom
__device__ float g_pacc[(size_t)BB * NCHUNK * HH]; // per-chunk unnormalized context
__device__ float g_pre[BB * 2 * HH];            // [context ; h_t]
__device__ float g_pout[JC * BB * UU];          // split-K partials of final GEMM

// ============================================================
// K1: split-K partial of v[b,h] = dot(w_score[h,:], h_t[b,:]).
// Block (hc, kc): 32 h-rows x 32 batches over k-range of 256.
// ============================================================
__global__ void k_v(const float* __restrict__ hidden, const float* __restrict__ wsc) {
    __shared__ float sht[32][65];
    __shared__ float swt[32][65];
    const int t = threadIdx.x;            // 256 threads
    const int h0 = blockIdx.x * 32;       // 32 h-chunks
    const int kbase = blockIdx.y * 256;   // 4 k-chunks

    float acc[4] = {0.f, 0.f, 0.f, 0.f};

    for (int k0 = kbase; k0 < kbase + 256; k0 += 64) {
        #pragma unroll
        for (int i = 0; i < 8; i++) {
            int idx = t + i * 256;
            int b = idx >> 6, k = idx & 63;
            sht[b][k] = hidden[((size_t)b * SS + (SS - 1)) * HH + k0 + k];
        }
        #pragma unroll
        for (int i = 0; i < 8; i++) {
            int idx = t + i * 256;
            int hh = idx >> 6, k = idx & 63;
            swt[hh][k] = wsc[(size_t)(h0 + hh) * HH + k0 + k];
        }
        __syncthreads();
        #pragma unroll
        for (int j = 0; j < 4; j++) {
            int o = t + j * 256;
            int b = o >> 5, hh = o & 31;
            float a = 0.f;
            #pragma unroll 8
            for (int k = 0; k < 64; k++) a += swt[hh][k] * sht[b][k];
            acc[j] += a;
        }
        __syncthreads();
    }
    #pragma unroll
    for (int j = 0; j < 4; j++) {
        int o = t + j * 256;
        int b = o >> 5, hh = o & 31;
        g_vp[((size_t)blockIdx.y * BB + b) * HH + h0 + hh] = acc[j];
    }
}

// ============================================================
// K2: barrier-free per-warp flash attention.
// Each warp owns 32 contiguous rows and the full H dim (8 float4/lane).
// Score = warp-shuffle reduce; online softmax entirely in registers.
// ============================================================
__global__ void __launch_bounds__(256) k_attn(const float* __restrict__ hidden) {
    const int b = blockIdx.y;
    const int w = threadIdx.x >> 5;
    const int l = threadIdx.x & 31;
    const int chunk = blockIdx.x * WPB + w;
    const int s0 = chunk * RPW;

    const float4* __restrict__ hid = reinterpret_cast<const float4*>(hidden) + (size_t)b * SS * H4;
    const float4* __restrict__ vp4 = reinterpret_cast<const float4*>(g_vp);

    // v[b] summed over split-K partials (held per-lane, 8 float4)
    float4 vv[8];
    #pragma unroll
    for (int j = 0; j < 8; j++) vv[j] = make_float4(0.f, 0.f, 0.f, 0.f);
    #pragma unroll
    for (int p = 0; p < KC; p++) {
        #pragma unroll
        for (int j = 0; j < 8; j++) {
            float4 a = vp4[((size_t)p * BB + b) * H4 + j * 32 + l];
            vv[j].x += a.x; vv[j].y += a.y; vv[j].z += a.z; vv[j].w += a.w;
        }
    }

    float4 acc[8];
    #pragma unroll
    for (int j = 0; j < 8; j++) acc[j] = make_float4(0.f, 0.f, 0.f, 0.f);
    float m = -INFINITY, L = 0.f;

    float4 cur[8];
    #pragma unroll
    for (int j = 0; j < 8; j++) cur[j] = hid[(size_t)s0 * H4 + j * 32 + l];

    for (int i = 0; i < RPW; i++) {
        float4 nxt[8];
        if (i + 1 < RPW) {
            #pragma unroll
            for (int j = 0; j < 8; j++) nxt[j] = hid[(size_t)(s0 + i + 1) * H4 + j * 32 + l];
        }

        float p = 0.f;
        #pragma unroll
        for (int j = 0; j < 8; j++)
            p += cur[j].x * vv[j].x + cur[j].y * vv[j].y + cur[j].z * vv[j].z + cur[j].w * vv[j].w;
        #pragma unroll
        for (int o = 16; o > 0; o >>= 1) p += __shfl_xor_sync(0xffffffffu, p, o);

        const float mn = fmaxf(m, p);
        const float sc = __expf(m - mn);   // 0 on first iter
        const float pp = __expf(p - mn);
        L = L * sc + pp;
        #pragma unroll
        for (int j = 0; j < 8; j++) {
            acc[j].x = acc[j].x * sc + pp * cur[j].x;
            acc[j].y = acc[j].y * sc + pp * cur[j].y;
            acc[j].z = acc[j].z * sc + pp * cur[j].z;
            acc[j].w = acc[j].w * sc + pp * cur[j].w;
        }
        m = mn;
        if (i + 1 < RPW) {
            #pragma unroll
            for (int j = 0; j < 8; j++) cur[j] = nxt[j];
        }
    }

    if (l == 0) { g_pm[b * NCHUNK + chunk] = m; g_pl[b * NCHUNK + chunk] = L; }
    float4* pacc4 = reinterpret_cast<float4*>(g_pacc);
    #pragma unroll
    for (int j = 0; j < 8; j++)
        pacc4[((size_t)b * NCHUNK + chunk) * H4 + j * 32 + l] = acc[j];
}

// ============================================================
// K3: merge 64 chunk partials -> context; build pre = [context ; h_t].
// Grid (B, 2): block covers 128 float4 of H.
// ============================================================
__global__ void k_combine(const float* __restrict__ hidden) {
    const int b = blockIdx.x;
    const int t = threadIdx.x;   // 128 threads
    __shared__ float sm[NCHUNK], sl[NCHUNK], wgt[NCHUNK];
    __shared__ float sinv;

    if (t < NCHUNK) { sm[t] = g_pm[b * NCHUNK + t]; sl[t] = g_pl[b * NCHUNK + t]; }
    __syncthreads();
    if (t == 0) {
        float M = -INFINITY;
        #pragma unroll
        for (int c = 0; c < NCHUNK; c++) M = fmaxf(M, sm[c]);
        float Ltot = 0.f;
        #pragma unroll
        for (int c = 0; c < NCHUNK; c++) {
            float e = __expf(sm[c] - M);
            wgt[c] = e;
            Ltot += sl[c] * e;
        }
        sinv = 1.f / Ltot;
    }
    __syncthreads();
    const float inv = sinv;

    const int hi = blockIdx.y * 128 + t;   // float4 index within H4
    const float4* pacc4 = reinterpret_cast<const float4*>(g_pacc);

    float4 ctx = make_float4(0.f, 0.f, 0.f, 0.f);
    #pragma unroll 4
    for (int c = 0; c < NCHUNK; c++) {
        const float e = wgt[c];
        const float4 a = pacc4[((size_t)b * NCHUNK + c) * H4 + hi];
        ctx.x += e * a.x; ctx.y += e * a.y; ctx.z += e * a.z; ctx.w += e * a.w;
    }
    ctx.x *= inv; ctx.y *= inv; ctx.z *= inv; ctx.w *= inv;

    float4* pre4 = reinterpret_cast<float4*>(g_pre);
    pre4[b * (2 * H4) + hi] = ctx;
    const float4 htv = reinterpret_cast<const float4*>(hidden)[((size_t)b * SS + (SS - 1)) * H4 + hi];
    pre4[b * (2 * H4) + H4 + hi] = htv;
}

// ============================================================
// K4: split-K output GEMM. Block p covers j in [p*32, p*32+32).
// 64 blocks x 128 threads (thread = output unit u, all 32 batches).
// ============================================================
__global__ void k_outp(const float* __restrict__ wout) {
    const int p = blockIdx.x;    // 64 blocks
    const int t = threadIdx.x;   // 128 threads
    const int j0 = p * JCW;

    __shared__ float spre[32][JCW];   // [b][jj], 4KB
    #pragma unroll
    for (int i = 0; i < 8; i++) {
        int idx = t + i * 128;
        int b = idx >> 5, jj = idx & 31;
        spre[b][jj] = g_pre[b * (2 * HH) + j0 + jj];
    }
    __syncthreads();

    float acc[32];
    #pragma unroll
    for (int b = 0; b < 32; b++) acc[b] = 0.f;

    #pragma unroll 4
    for (int jj = 0; jj < JCW; jj++) {
        const float wv = wout[(size_t)(j0 + jj) * UU + t];
        #pragma unroll
        for (int b = 0; b < 32; b++) acc[b] += spre[b][jj] * wv;
    }
    #pragma unroll
    for (int b = 0; b < 32; b++)
        g_pout[((size_t)p * BB + b) * UU + t] = acc[b];
}

// K5: reduce 64 partials + tanh -> output
__global__ void k_outf(float* __restrict__ out) {
    const int b = blockIdx.x;   // 32 blocks
    const int t = threadIdx.x;  // 128 threads
    float a = 0.f;
    #pragma unroll
    for (int p = 0; p < JC; p++) a += g_pout[((size_t)p * BB + b) * UU + t];
    out[b * UU + t] = tanhf(a);
}

extern "C" void kernel_launch(void* const* d_in, const int* in_sizes, int n_in,
                              void* d_out, int out_size) {
    const float* hidden = (const float*)d_in[0];  // (32, 2048, 1024) f32
    const float* wsc    = (const float*)d_in[1];  // (1024, 1024) f32
    const float* wout   = (const float*)d_in[2];  // (2048, 128) f32
    float* out = (float*)d_out;                   // (32, 128) f32

    k_v<<<dim3(32, KC), 256>>>(hidden, wsc);
    k_attn<<<dim3(NCB, BB), 256>>>(hidden);
    k_combine<<<dim3(BB, 2), 128>>>(hidden);
    k_outp<<<JC, 128>>>(wout);
    k_outf<<<BB, 128>>>(out);
}

// round 3
// speedup vs baseline: 1.5746x; 1.0867x over previous
#include <cuda_runtime.h>
#include <math.h>

#define BB 32
#define SS 2048
#define HH 1024
#define UU 128
#define H4 (HH / 4)        // 256 float4 per row
#define KC 4               // split-K for k_v
#define CH 16              // attn chunks per batch (one block each)
#define RPC (SS / CH)      // 128 rows per chunk
#define TILE 4             // rows per cp.async tile
#define NT (RPC / TILE)    // 32 tiles per block
#define JC2 64             // j-chunks for output GEMM
#define JCW (2 * HH / JC2) // 32 j-rows per chunk
#define BG 4               // batch groups for output GEMM

// ---- device scratch (no runtime allocation allowed) ----
__device__ float g_vp[KC * BB * HH];                // split-K partials of v = W @ h_t
__device__ float g_pm[BB * CH];                     // per-chunk running max
__device__ float g_pl[BB * CH];                     // per-chunk denom
__device__ float g_pacc[(size_t)BB * CH * HH];      // per-chunk unnormalized context
__device__ float g_pre[BB * 2 * HH];                // [context ; h_t]
__device__ float g_pout[JC2 * BB * UU];             // split-K partials of final GEMM

__device__ __forceinline__ void cp_async16(void* smem, const void* gmem) {
    unsigned saddr = (unsigned)__cvta_generic_to_shared(smem);
    asm volatile("cp.async.cg.shared.global [%0], [%1], 16;\n" :: "r"(saddr), "l"(gmem));
}
__device__ __forceinline__ void cp_commit() {
    asm volatile("cp.async.commit_group;\n" ::: "memory");
}
template <int N>
__device__ __forceinline__ void cp_wait() {
    asm volatile("cp.async.wait_group %0;\n" :: "n"(N) : "memory");
}

// ============================================================
// K1: split-K partial of v[b,h] = dot(w_score[h,:], h_t[b,:]).
// ============================================================
__global__ void k_v(const float* __restrict__ hidden, const float* __restrict__ wsc) {
    __shared__ float sht[32][65];
    __shared__ float swt[32][65];
    const int t = threadIdx.x;            // 256 threads
    const int h0 = blockIdx.x * 32;       // 32 h-chunks
    const int kbase = blockIdx.y * 256;   // 4 k-chunks

    float acc[4] = {0.f, 0.f, 0.f, 0.f};

    for (int k0 = kbase; k0 < kbase + 256; k0 += 64) {
        #pragma unroll
        for (int i = 0; i < 8; i++) {
            int idx = t + i * 256;
            int b = idx >> 6, k = idx & 63;
            sht[b][k] = hidden[((size_t)b * SS + (SS - 1)) * HH + k0 + k];
        }
        #pragma unroll
        for (int i = 0; i < 8; i++) {
            int idx = t + i * 256;
            int hh = idx >> 6, k = idx & 63;
            swt[hh][k] = wsc[(size_t)(h0 + hh) * HH + k0 + k];
        }
        __syncthreads();
        #pragma unroll
        for (int j = 0; j < 4; j++) {
            int o = t + j * 256;
            int b = o >> 5, hh = o & 31;
            float a = 0.f;
            #pragma unroll 8
            for (int k = 0; k < 64; k++) a += swt[hh][k] * sht[b][k];
            acc[j] += a;
        }
        __syncthreads();
    }
    #pragma unroll
    for (int j = 0; j < 4; j++) {
        int o = t + j * 256;
        int b = o >> 5, hh = o & 31;
        g_vp[((size_t)blockIdx.y * BB + b) * HH + h0 + hh] = acc[j];
    }
}

// ============================================================
// K2: cp.async double-buffered smem-tile flash attention.
// Block = (batch b, 128-row chunk). Tiles of 4 rows staged in smem.
// Thread t owns float4 slot t of H (acc = 4 regs). Scores from smem.
// ============================================================
__global__ void __launch_bounds__(256) k_attn(const float* __restrict__ hidden) {
    __shared__ float4 sv4[H4];                  // v[b], 4KB
    __shared__ float4 sbuf[2][TILE * H4];       // 2 x 16KB tile ring
    __shared__ float spart[TILE][2];            // per-row half-dot partials

    const int b = blockIdx.y;
    const int c = blockIdx.x;
    const int t = threadIdx.x;     // 256
    const int w = t >> 5;
    const int l = t & 31;
    const int s0 = c * RPC;

    const float4* __restrict__ hid = reinterpret_cast<const float4*>(hidden) + (size_t)b * SS * H4;
    const float4* __restrict__ vp4 = reinterpret_cast<const float4*>(g_vp);

    // v[b] = sum of split-K partials -> shared
    {
        float4 s = make_float4(0.f, 0.f, 0.f, 0.f);
        #pragma unroll
        for (int p = 0; p < KC; p++) {
            float4 a = vp4[((size_t)p * BB + b) * H4 + t];
            s.x += a.x; s.y += a.y; s.z += a.z; s.w += a.w;
        }
        sv4[t] = s;
    }

    // prologue: preload tiles 0 and 1
    #pragma unroll
    for (int pre = 0; pre < 2; pre++) {
        #pragma unroll
        for (int j = 0; j < TILE; j++)
            cp_async16(&sbuf[pre][j * H4 + t], &hid[(size_t)(s0 + pre * TILE + j) * H4 + t]);
        cp_commit();
    }

    float4 acc = make_float4(0.f, 0.f, 0.f, 0.f);
    float m = -INFINITY, L = 0.f;

    const int r = w >> 1;      // row handled by this warp for scoring
    const int hf = w & 1;      // which half of H

    for (int ti = 0; ti < NT; ti++) {
        const int bi = ti & 1;
        cp_wait<1>();
        __syncthreads();       // tile ti resident for all threads (also covers sv4 on ti==0)

        // scores: warp (r,hf) computes half-dot of row r with v
        {
            float p = 0.f;
            #pragma unroll
            for (int k = 0; k < 4; k++) {
                const int idx = hf * 128 + k * 32 + l;
                const float4 hv = sbuf[bi][r * H4 + idx];
                const float4 vv = sv4[idx];
                p += hv.x * vv.x + hv.y * vv.y + hv.z * vv.z + hv.w * vv.w;
            }
            #pragma unroll
            for (int o = 16; o > 0; o >>= 1) p += __shfl_xor_sync(0xffffffffu, p, o);
            if (l == 0) spart[r][hf] = p;
        }
        __syncthreads();

        // block-uniform online softmax update; thread t owns H-slot t
        float s[TILE];
        float mn = m;
        #pragma unroll
        for (int j = 0; j < TILE; j++) {
            s[j] = spart[j][0] + spart[j][1];
            mn = fmaxf(mn, s[j]);
        }
        const float sc = __expf(m - mn);   // 0 on first tile (m = -inf)
        float pp[TILE];
        #pragma unroll
        for (int j = 0; j < TILE; j++) pp[j] = __expf(s[j] - mn);

        acc.x *= sc; acc.y *= sc; acc.z *= sc; acc.w *= sc;
        float lsum = 0.f;
        #pragma unroll
        for (int j = 0; j < TILE; j++) {
            lsum += pp[j];
            const float4 hv = sbuf[bi][j * H4 + t];
            acc.x += pp[j] * hv.x;
            acc.y += pp[j] * hv.y;
            acc.z += pp[j] * hv.z;
            acc.w += pp[j] * hv.w;
        }
        L = L * sc + lsum;
        m = mn;
        __syncthreads();       // all done reading sbuf[bi] before refill

        if (ti + 2 < NT) {
            #pragma unroll
            for (int j = 0; j < TILE; j++)
                cp_async16(&sbuf[bi][j * H4 + t], &hid[(size_t)(s0 + (ti + 2) * TILE + j) * H4 + t]);
        }
        cp_commit();           // always commit to keep group arithmetic aligned
    }

    if (t == 0) { g_pm[b * CH + c] = m; g_pl[b * CH + c] = L; }
    reinterpret_cast<float4*>(g_pacc)[((size_t)b * CH + c) * H4 + t] = acc;
}

// ============================================================
// K3: merge 16 chunk partials -> context; build pre = [context ; h_t].
// ============================================================
__global__ void k_combine(const float* __restrict__ hidden) {
    const int b = blockIdx.x;
    const int t = threadIdx.x;   // 128 threads
    __shared__ float sm[CH], sl[CH], wgt[CH];
    __shared__ float sinv;

    if (t < CH) { sm[t] = g_pm[b * CH + t]; sl[t] = g_pl[b * CH + t]; }
    __syncthreads();
    if (t == 0) {
        float M = -INFINITY;
        #pragma unroll
        for (int c = 0; c < CH; c++) M = fmaxf(M, sm[c]);
        float Ltot = 0.f;
        #pragma unroll
        for (int c = 0; c < CH; c++) {
            float e = __expf(sm[c] - M);
            wgt[c] = e;
            Ltot += sl[c] * e;
        }
        sinv = 1.f / Ltot;
    }
    __syncthreads();
    const float inv = sinv;

    const int hi = blockIdx.y * 128 + t;
    const float4* pacc4 = reinterpret_cast<const float4*>(g_pacc);

    float4 ctx = make_float4(0.f, 0.f, 0.f, 0.f);
    #pragma unroll 4
    for (int c = 0; c < CH; c++) {
        const float e = wgt[c];
        const float4 a = pacc4[((size_t)b * CH + c) * H4 + hi];
        ctx.x += e * a.x; ctx.y += e * a.y; ctx.z += e * a.z; ctx.w += e * a.w;
    }
    ctx.x *= inv; ctx.y *= inv; ctx.z *= inv; ctx.w *= inv;

    float4* pre4 = reinterpret_cast<float4*>(g_pre);
    pre4[b * (2 * H4) + hi] = ctx;
    const float4 htv = reinterpret_cast<const float4*>(hidden)[((size_t)b * SS + (SS - 1)) * H4 + hi];
    pre4[b * (2 * H4) + H4 + hi] = htv;
}

// ============================================================
// K4: split-K output GEMM, (64 j-chunks x 4 batch-groups) blocks.
// Block (p, bg): j in [p*32, p*32+32), batches [bg*8, bg*8+8).
// ============================================================
__global__ void k_outp(const float* __restrict__ wout) {
    const int p = blockIdx.x;    // 64
    const int bg = blockIdx.y;   // 4
    const int t = threadIdx.x;   // 128 threads, t = output unit u
    const int j0 = p * JCW;
    const int b0 = bg * 8;

    __shared__ float spre[8][JCW];   // [brel][jj], 1KB
    #pragma unroll
    for (int i = 0; i < 2; i++) {
        int idx = t + i * 128;
        int br = idx >> 5, jj = idx & 31;
        spre[br][jj] = g_pre[(b0 + br) * (2 * HH) + j0 + jj];
    }
    __syncthreads();

    float acc[8];
    #pragma unroll
    for (int br = 0; br < 8; br++) acc[br] = 0.f;

    #pragma unroll 4
    for (int jj = 0; jj < JCW; jj++) {
        const float wv = wout[(size_t)(j0 + jj) * UU + t];
        #pragma unroll
        for (int br = 0; br < 8; br++) acc[br] += spre[br][jj] * wv;
    }
    #pragma unroll
    for (int br = 0; br < 8; br++)
        g_pout[((size_t)p * BB + b0 + br) * UU + t] = acc[br];
}

// K5: reduce 64 partials + tanh -> output
__global__ void k_outf(float* __restrict__ out) {
    const int b = blockIdx.x;   // 32 blocks
    const int t = threadIdx.x;  // 128 threads
    float a = 0.f;
    #pragma unroll
    for (int p = 0; p < JC2; p++) a += g_pout[((size_t)p * BB + b) * UU + t];
    out[b * UU + t] = tanhf(a);
}

extern "C" void kernel_launch(void* const* d_in, const int* in_sizes, int n_in,
                              void* d_out, int out_size) {
    const float* hidden = (const float*)d_in[0];  // (32, 2048, 1024) f32
    const float* wsc    = (const float*)d_in[1];  // (1024, 1024) f32
    const float* wout   = (const float*)d_in[2];  // (2048, 128) f32
    float* out = (float*)d_out;                   // (32, 128) f32

    k_v<<<dim3(32, KC), 256>>>(hidden, wsc);
    k_attn<<<dim3(CH, BB), 256>>>(hidden);
    k_combine<<<dim3(BB, 2), 128>>>(hidden);
    k_outp<<<dim3(JC2, BG), 128>>>(wout);
    k_outf<<<BB, 128>>>(out);
}

// round 4
// speedup vs baseline: 1.7552x; 1.1147x over previous
#include <cuda_runtime.h>
#include <math.h>

#define BB 32
#define SS 2048
#define HH 1024
#define UU 128
#define H4 (HH / 4)        // 256 float4 per row
#define KC 4               // split-K for k_v
#define CH 64              // attn chunks per batch (one block each)
#define RPC (SS / CH)      // 32 rows per chunk
#define TILE 2             // rows per cp.async tile (8 KB)
#define NT (RPC / TILE)    // 16 tiles per block
#define DEPTH 3            // ring depth
#define JC2 128            // j-chunks for output GEMM
#define JCW (2 * HH / JC2) // 16 j-rows per chunk
#define BG 4               // batch groups for output GEMM

// ---- device scratch (no runtime allocation allowed) ----
__device__ float g_vp[KC * BB * HH];                // split-K partials of v = W @ h_t
__device__ float g_pm[BB * CH];                     // per-chunk running max
__device__ float g_pl[BB * CH];                     // per-chunk denom
__device__ float g_pacc[(size_t)BB * CH * HH];      // per-chunk unnormalized context (8 MB)
__device__ float g_pre[BB * 2 * HH];                // [context ; h_t]
__device__ float g_pout[JC2 * BB * UU];             // split-K partials of final GEMM (2 MB)

__device__ __forceinline__ void cp_async16(void* smem, const void* gmem) {
    unsigned saddr = (unsigned)__cvta_generic_to_shared(smem);
    asm volatile("cp.async.cg.shared.global [%0], [%1], 16;\n" :: "r"(saddr), "l"(gmem));
}
__device__ __forceinline__ void cp_commit() {
    asm volatile("cp.async.commit_group;\n" ::: "memory");
}
template <int N>
__device__ __forceinline__ void cp_wait() {
    asm volatile("cp.async.wait_group %0;\n" :: "n"(N) : "memory");
}

// ============================================================
// K1: split-K partial of v[b,h] = dot(w_score[h,:], h_t[b,:]).
// ============================================================
__global__ void k_v(const float* __restrict__ hidden, const float* __restrict__ wsc) {
    __shared__ float sht[32][65];
    __shared__ float swt[32][65];
    const int t = threadIdx.x;            // 256 threads
    const int h0 = blockIdx.x * 32;       // 32 h-chunks
    const int kbase = blockIdx.y * 256;   // 4 k-chunks

    float acc[4] = {0.f, 0.f, 0.f, 0.f};

    for (int k0 = kbase; k0 < kbase + 256; k0 += 64) {
        #pragma unroll
        for (int i = 0; i < 8; i++) {
            int idx = t + i * 256;
            int b = idx >> 6, k = idx & 63;
            sht[b][k] = hidden[((size_t)b * SS + (SS - 1)) * HH + k0 + k];
        }
        #pragma unroll
        for (int i = 0; i < 8; i++) {
            int idx = t + i * 256;
            int hh = idx >> 6, k = idx & 63;
            swt[hh][k] = wsc[(size_t)(h0 + hh) * HH + k0 + k];
        }
        __syncthreads();
        #pragma unroll
        for (int j = 0; j < 4; j++) {
            int o = t + j * 256;
            int b = o >> 5, hh = o & 31;
            float a = 0.f;
            #pragma unroll 8
            for (int k = 0; k < 64; k++) a += swt[hh][k] * sht[b][k];
            acc[j] += a;
        }
        __syncthreads();
    }
    #pragma unroll
    for (int j = 0; j < 4; j++) {
        int o = t + j * 256;
        int b = o >> 5, hh = o & 31;
        g_vp[((size_t)blockIdx.y * BB + b) * HH + h0 + hh] = acc[j];
    }
}

// ============================================================
// K2: cp.async triple-buffered smem-tile flash attention.
// Block = (batch b, 32-row chunk). Tiles of 2 rows in a depth-3 ring.
// Loads for tile ti+2 issued BEFORE compute of tile ti. 2 syncs/tile.
// ============================================================
__global__ void __launch_bounds__(256) k_attn(const float* __restrict__ hidden) {
    __shared__ float4 sv4[H4];                    // v[b], 4KB
    __shared__ float4 sbuf[DEPTH][TILE * H4];     // 3 x 8KB tile ring
    __shared__ float spart[TILE][4];              // per-row quarter-dot partials

    const int b = blockIdx.y;
    const int c = blockIdx.x;
    const int t = threadIdx.x;     // 256
    const int w = t >> 5;
    const int l = t & 31;
    const int s0 = c * RPC;

    const float4* __restrict__ hid = reinterpret_cast<const float4*>(hidden) + (size_t)b * SS * H4;
    const float4* __restrict__ vp4 = reinterpret_cast<const float4*>(g_vp);

    // v[b] = sum of split-K partials -> shared
    {
        float4 s = make_float4(0.f, 0.f, 0.f, 0.f);
        #pragma unroll
        for (int p = 0; p < KC; p++) {
            float4 a = vp4[((size_t)p * BB + b) * H4 + t];
            s.x += a.x; s.y += a.y; s.z += a.z; s.w += a.w;
        }
        sv4[t] = s;
    }

    // prologue: preload tiles 0 and 1 into slots 0,1
    #pragma unroll
    for (int pre = 0; pre < 2; pre++) {
        #pragma unroll
        for (int j = 0; j < TILE; j++)
            cp_async16(&sbuf[pre][j * H4 + t], &hid[(size_t)(s0 + pre * TILE + j) * H4 + t]);
        cp_commit();
    }

    float4 acc = make_float4(0.f, 0.f, 0.f, 0.f);
    float m = -INFINITY, L = 0.f;

    const int r = w >> 2;      // row (0..1) this warp scores
    const int q = w & 3;       // quarter of H

    for (int ti = 0; ti < NT; ti++) {
        const int slot = ti % DEPTH;
        cp_wait<1>();
        __syncthreads();       // tile ti resident (also covers sv4 on ti==0)

        // issue loads for tile ti+2 into slot (ti+2)%DEPTH (held tile ti-1,
        // fully consumed before the barrier above) BEFORE computing.
        if (ti + 2 < NT) {
            const int ns = (ti + 2) % DEPTH;
            #pragma unroll
            for (int j = 0; j < TILE; j++)
                cp_async16(&sbuf[ns][j * H4 + t], &hid[(size_t)(s0 + (ti + 2) * TILE + j) * H4 + t]);
        }
        cp_commit();           // always commit to keep group arithmetic aligned

        // scores: warp (r,q) computes quarter-dot of row r with v
        {
            float p = 0.f;
            #pragma unroll
            for (int k = 0; k < 2; k++) {
                const int idx = q * 64 + k * 32 + l;
                const float4 hv = sbuf[slot][r * H4 + idx];
                const float4 vv = sv4[idx];
                p += hv.x * vv.x + hv.y * vv.y + hv.z * vv.z + hv.w * vv.w;
            }
            #pragma unroll
            for (int o = 16; o > 0; o >>= 1) p += __shfl_xor_sync(0xffffffffu, p, o);
            if (l == 0) spart[r][q] = p;
        }
        __syncthreads();

        // block-uniform online softmax update; thread t owns H-slot t
        float s[TILE];
        float mn = m;
        #pragma unroll
        for (int j = 0; j < TILE; j++) {
            s[j] = spart[j][0] + spart[j][1] + spart[j][2] + spart[j][3];
            mn = fmaxf(mn, s[j]);
        }
        const float sc = __expf(m - mn);   // 0 on first tile (m = -inf)
        float pp[TILE];
        #pragma unroll
        for (int j = 0; j < TILE; j++) pp[j] = __expf(s[j] - mn);

        acc.x *= sc; acc.y *= sc; acc.z *= sc; acc.w *= sc;
        float lsum = 0.f;
        #pragma unroll
        for (int j = 0; j < TILE; j++) {
            lsum += pp[j];
            const float4 hv = sbuf[slot][j * H4 + t];
            acc.x += pp[j] * hv.x;
            acc.y += pp[j] * hv.y;
            acc.z += pp[j] * hv.z;
            acc.w += pp[j] * hv.w;
        }
        L = L * sc + lsum;
        m = mn;
        // no trailing barrier: depth-3 ring + next iteration's barrier protect reuse
    }

    if (t == 0) { g_pm[b * CH + c] = m; g_pl[b * CH + c] = L; }
    reinterpret_cast<float4*>(g_pacc)[((size_t)b * CH + c) * H4 + t] = acc;
}

// ============================================================
// K3: merge 64 chunk partials -> context; build pre = [context ; h_t].
// Grid (B, 4) x 64 threads; weights recomputed per-thread (no serial section).
// ============================================================
__global__ void k_combine(const float* __restrict__ hidden) {
    const int b = blockIdx.x;
    const int t = threadIdx.x;   // 64 threads
    __shared__ float sm[CH], sl[CH];

    sm[t] = g_pm[b * CH + t];
    sl[t] = g_pl[b * CH + t];
    __syncthreads();

    float M = -INFINITY;
    #pragma unroll
    for (int c = 0; c < CH; c++) M = fmaxf(M, sm[c]);
    float Ltot = 0.f;
    #pragma unroll
    for (int c = 0; c < CH; c++) Ltot += sl[c] * __expf(sm[c] - M);
    const float inv = 1.f / Ltot;

    const int hi = blockIdx.y * 64 + t;   // float4 index within H4
    const float4* pacc4 = reinterpret_cast<const float4*>(g_pacc);

    float4 ctx = make_float4(0.f, 0.f, 0.f, 0.f);
    #pragma unroll 4
    for (int c = 0; c < CH; c++) {
        const float e = __expf(sm[c] - M);
        const float4 a = pacc4[((size_t)b * CH + c) * H4 + hi];
        ctx.x += e * a.x; ctx.y += e * a.y; ctx.z += e * a.z; ctx.w += e * a.w;
    }
    ctx.x *= inv; ctx.y *= inv; ctx.z *= inv; ctx.w *= inv;

    float4* pre4 = reinterpret_cast<float4*>(g_pre);
    pre4[b * (2 * H4) + hi] = ctx;
    const float4 htv = reinterpret_cast<const float4*>(hidden)[((size_t)b * SS + (SS - 1)) * H4 + hi];
    pre4[b * (2 * H4) + H4 + hi] = htv;
}

// ============================================================
// K4: split-K output GEMM, (128 j-chunks x 4 batch-groups) = 512 blocks.
// Block (p, bg): j in [p*16, p*16+16), batches [bg*8, bg*8+8).
// ============================================================
__global__ void k_outp(const float* __restrict__ wout) {
    const int p = blockIdx.x;    // 128
    const int bg = blockIdx.y;   // 4
    const int t = threadIdx.x;   // 128 threads, t = output unit u
    const int j0 = p * JCW;
    const int b0 = bg * 8;

    __shared__ float spre[8][JCW];   // [brel][jj], 512B
    {
        int br = t >> 4, jj = t & 15;
        spre[br][jj] = g_pre[(b0 + br) * (2 * HH) + j0 + jj];
    }
    __syncthreads();

    float acc[8];
    #pragma unroll
    for (int br = 0; br < 8; br++) acc[br] = 0.f;

    #pragma unroll
    for (int jj = 0; jj < JCW; jj++) {
        const float wv = wout[(size_t)(j0 + jj) * UU + t];
        #pragma unroll
        for (int br = 0; br < 8; br++) acc[br] += spre[br][jj] * wv;
    }
    #pragma unroll
    for (int br = 0; br < 8; br++)
        g_pout[((size_t)p * BB + b0 + br) * UU + t] = acc[br];
}

// K5: reduce 128 partials + tanh -> output
__global__ void k_outf(float* __restrict__ out) {
    const int b = blockIdx.x;   // 32 blocks
    const int t = threadIdx.x;  // 128 threads
    float a = 0.f;
    #pragma unroll
    for (int p = 0; p < JC2; p++) a += g_pout[((size_t)p * BB + b) * UU + t];
    out[b * UU + t] = tanhf(a);
}

extern "C" void kernel_launch(void* const* d_in, const int* in_sizes, int n_in,
                              void* d_out, int out_size) {
    const float* hidden = (const float*)d_in[0];  // (32, 2048, 1024) f32
    const float* wsc    = (const float*)d_in[1];  // (1024, 1024) f32
    const float* wout   = (const float*)d_in[2];  // (2048, 128) f32
    float* out = (float*)d_out;                   // (32, 128) f32

    k_v<<<dim3(32, KC), 256>>>(hidden, wsc);
    k_attn<<<dim3(CH, BB), 256>>>(hidden);
    k_combine<<<dim3(BB, 4), 64>>>(hidden);
    k_outp<<<dim3(JC2, BG), 128>>>(wout);
    k_outf<<<BB, 128>>>(out);
}

// round 7
// speedup vs baseline: 1.9556x; 1.1142x over previous
#include <cuda_runtime.h>
#include <math.h>

#define BB 32
#define SS 2048
#define HH 1024
#define UU 128
#define H4 (HH / 4)        // 256 float4 per row
#define KC 8               // split-K for k_v
#define CH 64              // attn chunks per batch (one block each)
#define RPC (SS / CH)      // 32 rows per chunk
#define TILE 2             // rows per cp.async tile (8 KB)
#define NT (RPC / TILE)    // 16 tiles per block
#define DEPTH 3            // ring depth
#define JC2 128            // j-chunks for output GEMM
#define JCW (2 * HH / JC2) // 16 j-rows per chunk
#define BG 8               // batch groups for output GEMM (4 batches each)

// ---- device scratch (no runtime allocation allowed) ----
__device__ float g_vp[KC * BB * HH];                // split-K partials of v = W @ h_t
__device__ float g_pm[BB * CH];                     // per-chunk running max
__device__ float g_pl[BB * CH];                     // per-chunk denom
__device__ float g_pacc[(size_t)BB * CH * HH];      // per-chunk unnormalized context (8 MB)
__device__ float g_pre[BB * 2 * HH];                // [context ; h_t]
__device__ float g_pout[JC2 * BB * UU];             // split-K partials of final GEMM (2 MB)

__device__ __forceinline__ void cp_async16(void* smem, const void* gmem) {
    unsigned saddr = (unsigned)__cvta_generic_to_shared(smem);
    asm volatile("cp.async.cg.shared.global [%0], [%1], 16;\n" :: "r"(saddr), "l"(gmem));
}
__device__ __forceinline__ void cp_commit() {
    asm volatile("cp.async.commit_group;\n" ::: "memory");
}
template <int N>
__device__ __forceinline__ void cp_wait() {
    asm volatile("cp.async.wait_group %0;\n" :: "n"(N) : "memory");
}

// ============================================================
// K1: split-K partial of v[b,h] = dot(w_score[h,:], h_t[b,:]).
// Grid (64 h-chunks, 8 k-chunks) = 512 blocks. One-shot tiles, 1 barrier.
// ============================================================
__global__ void __launch_bounds__(256) k_v(const float* __restrict__ hidden,
                                           const float* __restrict__ wsc) {
    __shared__ float sht[32][132];   // 32 b x 128 k (+4 pad)
    __shared__ float swt[16][132];   // 16 h x 128 k (+4 pad)
    const int t = threadIdx.x;              // 256 threads
    const int h0 = blockIdx.x * 16;         // 64 h-chunks
    const int kb4 = blockIdx.y * 32;        // k-chunk base in float4 units (128 floats)

    const float4* __restrict__ hid4 = reinterpret_cast<const float4*>(hidden);
    const float4* __restrict__ wsc4 = reinterpret_cast<const float4*>(wsc);

    // load h_t tile: 32 b x 32 float4
    #pragma unroll
    for (int i = 0; i < 4; i++) {
        int fi = t + i * 256;
        int b = fi >> 5, k4 = fi & 31;
        float4 v = hid4[((size_t)b * SS + (SS - 1)) * H4 + kb4 + k4];
        *reinterpret_cast<float4*>(&sht[b][k4 * 4]) = v;
    }
    // load wsc tile: 16 h x 32 float4
    #pragma unroll
    for (int i = 0; i < 2; i++) {
        int fi = t + i * 256;
        int h = fi >> 5, k4 = fi & 31;
        float4 v = wsc4[(size_t)(h0 + h) * H4 + kb4 + k4];
        *reinterpret_cast<float4*>(&swt[h][k4 * 4]) = v;
    }
    __syncthreads();

    #pragma unroll
    for (int j = 0; j < 2; j++) {
        int o = t + j * 256;
        int b = o >> 4, h = o & 15;
        float a = 0.f;
        #pragma unroll 8
        for (int k = 0; k < 128; k++) a += swt[h][k] * sht[b][k];
        g_vp[((size_t)blockIdx.y * BB + b) * HH + h0 + h] = a;
    }
}

// ============================================================
// K2: pipelined smem-tile flash attention, ONE barrier per tile.
// Score of tile ti+1 overlaps accumulation of tile ti (double-buffered spart).
// v slice held in registers per scoring warp.
// ============================================================
__global__ void __launch_bounds__(256) k_attn(const float* __restrict__ hidden) {
    __shared__ float4 sbuf[DEPTH][TILE * H4];     // 3 x 8KB tile ring
    __shared__ float spart[2][TILE][4];           // double-buffered quarter-dot partials

    const int b = blockIdx.y;
    const int c = blockIdx.x;
    const int t = threadIdx.x;     // 256
    const int w = t >> 5;
    const int l = t & 31;
    const int r = w >> 2;          // row (0..1) this warp scores
    const int q = w & 3;           // quarter of H
    const int s0 = c * RPC;

    const float4* __restrict__ hid = reinterpret_cast<const float4*>(hidden) + (size_t)b * SS * H4;
    const float4* __restrict__ vp4 = reinterpret_cast<const float4*>(g_vp);

    // v slice for this scoring warp: 2 float4/lane, summed over KC partials
    const int vi0 = q * 64 + l;
    const int vi1 = q * 64 + 32 + l;
    float4 vv0 = make_float4(0.f, 0.f, 0.f, 0.f);
    float4 vv1 = make_float4(0.f, 0.f, 0.f, 0.f);
    #pragma unroll
    for (int p = 0; p < KC; p++) {
        float4 a = vp4[((size_t)p * BB + b) * H4 + vi0];
        float4 e = vp4[((size_t)p * BB + b) * H4 + vi1];
        vv0.x += a.x; vv0.y += a.y; vv0.z += a.z; vv0.w += a.w;
        vv1.x += e.x; vv1.y += e.y; vv1.z += e.z; vv1.w += e.w;
    }

    // preload tiles 0,1
    #pragma unroll
    for (int pre = 0; pre < 2; pre++) {
        #pragma unroll
        for (int j = 0; j < TILE; j++)
            cp_async16(&sbuf[pre][j * H4 + t], &hid[(size_t)(s0 + pre * TILE + j) * H4 + t]);
        cp_commit();
    }

    // prologue: score tile 0 into spart[0]
    cp_wait<1>();
    __syncthreads();
    {
        const float4 h0v = sbuf[0][r * H4 + vi0];
        const float4 h1v = sbuf[0][r * H4 + vi1];
        float p = h0v.x * vv0.x + h0v.y * vv0.y + h0v.z * vv0.z + h0v.w * vv0.w
                + h1v.x * vv1.x + h1v.y * vv1.y + h1v.z * vv1.z + h1v.w * vv1.w;
        #pragma unroll
        for (int o = 16; o > 0; o >>= 1) p += __shfl_xor_sync(0xffffffffu, p, o);
        if (l == 0) spart[0][r][q] = p;
    }

    float4 acc = make_float4(0.f, 0.f, 0.f, 0.f);
    float m = -INFINITY, L = 0.f;

    for (int ti = 0; ti < NT; ti++) {
        // (a) issue loads for tile ti+2 (slot's old tenant fully consumed)
        if (ti + 2 < NT) {
            const int ns = (ti + 2) % DEPTH;
            #pragma unroll
            for (int j = 0; j < TILE; j++)
                cp_async16(&sbuf[ns][j * H4 + t], &hid[(size_t)(s0 + (ti + 2) * TILE + j) * H4 + t]);
        }
        cp_commit();

        // (b) tile ti+1 resident; spart[ti&1] (written last iter / prologue) visible
        cp_wait<1>();
        __syncthreads();

        // (c) score tile ti+1 into spart[(ti+1)&1]
        if (ti + 1 < NT) {
            const int s1 = (ti + 1) % DEPTH;
            const float4 h0v = sbuf[s1][r * H4 + vi0];
            const float4 h1v = sbuf[s1][r * H4 + vi1];
            float p = h0v.x * vv0.x + h0v.y * vv0.y + h0v.z * vv0.z + h0v.w * vv0.w
                    + h1v.x * vv1.x + h1v.y * vv1.y + h1v.z * vv1.z + h1v.w * vv1.w;
            #pragma unroll
            for (int o = 16; o > 0; o >>= 1) p += __shfl_xor_sync(0xffffffffu, p, o);
            if (l == 0) spart[(ti + 1) & 1][r][q] = p;
        }

        // (d) softmax + accumulate tile ti (reads spart[ti&1], other buffer)
        {
            const int slot = ti % DEPTH;
            const float* sp0 = spart[ti & 1][0];
            const float* sp1 = spart[ti & 1][1];
            const float sA = sp0[0] + sp0[1] + sp0[2] + sp0[3];
            const float sB = sp1[0] + sp1[1] + sp1[2] + sp1[3];
            const float mn = fmaxf(m, fmaxf(sA, sB));
            const float sc = __expf(m - mn);    // 0 on first tile
            const float pA = __expf(sA - mn);
            const float pB = __expf(sB - mn);
            const float4 hA = sbuf[slot][t];
            const float4 hB = sbuf[slot][H4 + t];
            acc.x = acc.x * sc + pA * hA.x + pB * hB.x;
            acc.y = acc.y * sc + pA * hA.y + pB * hB.y;
            acc.z = acc.z * sc + pA * hA.z + pB * hB.z;
            acc.w = acc.w * sc + pA * hA.w + pB * hB.w;
            L = L * sc + pA + pB;
            m = mn;
        }
    }

    if (t == 0) { g_pm[b * CH + c] = m; g_pl[b * CH + c] = L; }
    reinterpret_cast<float4*>(g_pacc)[((size_t)b * CH + c) * H4 + t] = acc;
}

// ============================================================
// K3: merge 64 chunk partials -> context; build pre = [context ; h_t].
// Grid (B, 4) x 256: thread (cg, hi) sums 16 chunks; smem reduce over cg.
// ============================================================
__global__ void __launch_bounds__(256) k_combine(const float* __restrict__ hidden) {
    const int b = blockIdx.x;
    const int t = threadIdx.x;      // 256
    const int cg = t >> 6;          // 0..3
    const int hl = t & 63;
    __shared__ float sm[CH], sl[CH], wgt[CH];
    __shared__ float sinv;
    __shared__ float4 red[4][64];

    if (t < CH) { sm[t] = g_pm[b * CH + t]; sl[t] = g_pl[b * CH + t]; }
    __syncthreads();

    if (t < 32) {
        // warp 0: weights + 1/L
        float M = fmaxf(sm[t], sm[t + 32]);
        #pragma unroll
        for (int o = 16; o > 0; o >>= 1) M = fmaxf(M, __shfl_xor_sync(0xffffffffu, M, o));
        float e0 = __expf(sm[t] - M), e1 = __expf(sm[t + 32] - M);
        wgt[t] = e0; wgt[t + 32] = e1;
        float Lp = sl[t] * e0 + sl[t + 32] * e1;
        #pragma unroll
        for (int o = 16; o > 0; o >>= 1) Lp += __shfl_xor_sync(0xffffffffu, Lp, o);
        if (t == 0) sinv = 1.f / Lp;
    }
    __syncthreads();

    const int hi = blockIdx.y * 64 + hl;   // float4 index within H4
    const float4* pacc4 = reinterpret_cast<const float4*>(g_pacc);

    float4 ctx = make_float4(0.f, 0.f, 0.f, 0.f);
    #pragma unroll
    for (int cc = 0; cc < 16; cc++) {
        const int c = cg * 16 + cc;
        const float e = wgt[c];
        const float4 a = pacc4[((size_t)b * CH + c) * H4 + hi];
        ctx.x += e * a.x; ctx.y += e * a.y; ctx.z += e * a.z; ctx.w += e * a.w;
    }
    red[cg][hl] = ctx;
    __syncthreads();

    if (cg == 0) {
        const float inv = sinv;
        float4 s = red[0][hl], a1 = red[1][hl], a2 = red[2][hl], a3 = red[3][hl];
        s.x = (s.x + a1.x + a2.x + a3.x) * inv;
        s.y = (s.y + a1.y + a2.y + a3.y) * inv;
        s.z = (s.z + a1.z + a2.z + a3.z) * inv;
        s.w = (s.w + a1.w + a2.w + a3.w) * inv;
        float4* pre4 = reinterpret_cast<float4*>(g_pre);
        pre4[b * (2 * H4) + hi] = s;
        pre4[b * (2 * H4) + H4 + hi] =
            reinterpret_cast<const float4*>(hidden)[((size_t)b * SS + (SS - 1)) * H4 + hi];
    }
}

// ============================================================
// K4: split-K output GEMM, (128 j-chunks x 8 batch-groups) = 1024 blocks.
// Thread (brel, u4): float4 of U for 4 batches; wout read as float4.
// ============================================================
__global__ void __launch_bounds__(128) k_outp(const float* __restrict__ wout) {
    const int p = blockIdx.x;     // 128
    const int bg = blockIdx.y;    // 8
    const int t = threadIdx.x;    // 128
    const int u4 = t & 31;
    const int brel = t >> 5;      // 0..3
    const int j0 = p * JCW;
    const int b0 = bg * 4;

    __shared__ float spre[4][JCW];   // 256B
    if (t < 64) spre[t >> 4][t & 15] = g_pre[(b0 + (t >> 4)) * (2 * HH) + j0 + (t & 15)];
    __syncthreads();

    const float4* __restrict__ wo4 = reinterpret_cast<const float4*>(wout);
    float4 acc = make_float4(0.f, 0.f, 0.f, 0.f);
    const float* myp = spre[brel];

    #pragma unroll
    for (int jj = 0; jj < JCW; jj++) {
        const float4 wv = wo4[(size_t)(j0 + jj) * 32 + u4];
        const float pr = myp[jj];
        acc.x += pr * wv.x; acc.y += pr * wv.y; acc.z += pr * wv.z; acc.w += pr * wv.w;
    }
    reinterpret_cast<float4*>(g_pout)[((size_t)p * BB + b0 + brel) * 32 + u4] = acc;
}

// K5: reduce 128 partials (8-way split + smem reduce) + tanh -> output
__global__ void __launch_bounds__(256) k_outf(float* __restrict__ out) {
    const int b = blockIdx.x;   // 32 blocks
    const int t = threadIdx.x;  // 256
    const int u4 = t & 31;
    const int pg = t >> 5;      // 0..7
    __shared__ float4 red[8][32];

    const float4* __restrict__ po4 = reinterpret_cast<const float4*>(g_pout);
    float4 a = make_float4(0.f, 0.f, 0.f, 0.f);
    #pragma unroll
    for (int pp = 0; pp < 16; pp++) {
        const int p = pg * 16 + pp;
        const float4 v = po4[((size_t)p * BB + b) * 32 + u4];
        a.x += v.x; a.y += v.y; a.z += v.z; a.w += v.w;
    }
    red[pg][u4] = a;
    __syncthreads();

    if (pg == 0) {
        float4 s = red[0][u4];
        #pragma unroll
        for (int g = 1; g < 8; g++) {
            const float4 v = red[g][u4];
            s.x += v.x; s.y += v.y; s.z += v.z; s.w += v.w;
        }
        s.x = tanhf(s.x); s.y = tanhf(s.y); s.z = tanhf(s.z); s.w = tanhf(s.w);
        reinterpret_cast<float4*>(out)[b * 32 + u4] = s;
    }
}

extern "C" void kernel_launch(void* const* d_in, const int* in_sizes, int n_in,
                              void* d_out, int out_size) {
    const float* hidden = (const float*)d_in[0];  // (32, 2048, 1024) f32
    const float* wsc    = (const float*)d_in[1];  // (1024, 1024) f32
    const float* wout   = (const float*)d_in[2];  // (2048, 128) f32
    float* out = (float*)d_out;                   // (32, 128) f32

    k_v<<<dim3(64, KC), 256>>>(hidden, wsc);
    k_attn<<<dim3(CH, BB), 256>>>(hidden);
    k_combine<<<dim3(BB, 4), 256>>>(hidden);
    k_outp<<<dim3(JC2, BG), 128>>>(wout);
    k_outf<<<BB, 256>>>(out);
}